// round 16
// baseline (speedup 1.0000x reference)
#include <cuda_runtime.h>
#include <math.h>
#include <stdint.h>

#define NBATCH 2
#define CHN 64
#define NY 80
#define NX 80
#define NCLS 80
#define KTOT (NCLS*NY*NX)   /* 512000 */
#define NO 85
#define OC3 192
#define NU 84
#define ELEMS_PER_BATCH (KTOT * NO)      /* 43,520,000 */
#define EPB4 (ELEMS_PER_BATCH / 4)       /* 10,880,000 float4 per batch */
#define CTAS_PER_BATCH (EPB4 / 1024)     /* 10,625 — exact, no straddle */

typedef unsigned long long ull;

/* ---------------- device scratch ---------------- */
/* conv weights, scalar f32: [ci][ocg(64)][36] (27 used; 144B stride is
   conflict-free across the 8 ocg of a warp)                              */
#define W_OCG_STR 36
#define W_CI_FL  (64 * W_OCG_STR)         /* 2304 floats per ci slab */
#define W_CI_C16 (W_CI_FL / 4)            /* 576 16B chunks per slab */
__device__ float g_w1s[64 * W_CI_FL];
__device__ float g_w2[NU * 64];
__device__ float g_b1[OC3];
__device__ float g_b2[NU];
__device__ float g_hm[NBATCH * KTOT];
__device__ float g_xywh[NBATCH * NY * NX * 4];
__device__ unsigned int g_ballot[1000 * 32];
__device__ int g_bcount[1000];
__device__ int g_boff[1000];
__device__ int g_total[NBATCH];

/* ---------------- helpers ---------------- */
__device__ __forceinline__ void fma2(ull& d, ull a, ull b) {
    asm("fma.rn.f32x2 %0, %1, %2, %0;" : "+l"(d) : "l"(a), "l"(b));
}
__device__ __forceinline__ float2 unpack2(ull v) {
    float2 r;
    asm("mov.b64 {%0, %1}, %2;" : "=f"(r.x), "=f"(r.y) : "l"(v));
    return r;
}
__device__ __forceinline__ ull pack2f(float lo, float hi) {
    ull r;
    asm("mov.b64 %0, {%1, %2};" : "=l"(r) : "f"(lo), "f"(hi));
    return r;
}
__device__ __forceinline__ void cp_async16(uint32_t s, const void* g) {
    asm volatile("cp.async.cg.shared.global [%0], [%1], 16;" :: "r"(s), "l"(g));
}
__device__ __forceinline__ void cp_commit() {
    asm volatile("cp.async.commit_group;");
}
__device__ __forceinline__ void cp_wait1() {
    asm volatile("cp.async.wait_group 1;");
}
__device__ __forceinline__ uint32_t smem_u32(const void* p) {
    return (uint32_t)__cvta_generic_to_shared(p);
}

/* ---------------- weight prep ---------------- */
__global__ void prep_w1(const float* __restrict__ hm, const float* __restrict__ wh,
                        const float* __restrict__ rg) {
    int idx = blockIdx.x * 256 + threadIdx.x;
    if (idx >= 64 * W_CI_FL) return;
    int ci   = idx / W_CI_FL;
    int rem  = idx - ci * W_CI_FL;
    int ocg  = rem / W_OCG_STR;
    int j    = rem - ocg * W_OCG_STR;
    float w = 0.f;
    if (j < 27) {
        int hr = j / 9;
        int k9 = j - hr * 9;
        int o  = k9 / 3;
        int k  = k9 - o * 3;
        int oc = ocg * 3 + o;
        const float* src = (oc < 64) ? hm : (oc < 128) ? wh : rg;
        int o64 = oc & 63;
        w = src[o64 * 576 + ci * 9 + hr * 3 + k];
    }
    g_w1s[idx] = w;
}

__global__ void prep_rest(const float* __restrict__ hm_b1, const float* __restrict__ wh_b1,
                          const float* __restrict__ reg_b1,
                          const float* __restrict__ hm_w2, const float* __restrict__ wh_w2,
                          const float* __restrict__ reg_w2,
                          const float* __restrict__ hm_b2, const float* __restrict__ wh_b2,
                          const float* __restrict__ reg_b2) {
    int t = blockIdx.x * 256 + threadIdx.x;
    if (t < OC3) g_b1[t] = (t < 64) ? hm_b1[t] : (t < 128) ? wh_b1[t - 64] : reg_b1[t - 128];
    if (t < NU)  g_b2[t] = (t < 80) ? hm_b2[t] : (t < 82) ? wh_b2[t - 80] : reg_b2[t - 82];
    if (t < NU * 64) {
        int u = t >> 6, ci = t & 63;
        g_w2[t] = (u < 80) ? hm_w2[u * 64 + ci]
                : (u < 82) ? wh_w2[(u - 80) * 64 + ci]
                           : reg_w2[(u - 82) * 64 + ci];
    }
}

__global__ void dummy_kernel() {}

/* ---------------- fused conv kernel (R11 best: 104.4us) ----------------
   Tile 8x4 px, 256 threads, occ 3.  Thread = (r=tid&3, ocg=tid>>2): 3 oc,
   4 pixel-pairs.  Single input copy; operand pairs via register packing.
   Scalar-f32 weight slabs, ocg-stride 36 (conflict-free), 3-buffer
   cp.async pipeline, one barrier per ci.                                 */
#define TTX 8
#define TTY 4
#define S_IN_FL   (64 * 6 * 12)      /* 4608 floats */
#define O_WS      S_IN_FL
#define W_BUF_FL  W_CI_FL            /* 2304 floats per buffer */
#define MAIN_FL   (O_WS + 3 * W_BUF_FL)    /* 11520 floats = 46 kB */
#define S_U_STR   193
#define S_U_FL    (32 * S_U_STR)
#define O_W2      S_U_FL
#define S_W2_STR  65
#define S_W2_FL   (NU * S_W2_STR)
#define O_B2      (O_W2 + S_W2_FL)
#define POST_FL   (O_B2 + NU)        /* 11720 */
#define SMEM_FL   (POST_FL > MAIN_FL ? POST_FL : MAIN_FL)
#define SMEM_BYTES (SMEM_FL * 4)

__global__ __launch_bounds__(256, 3) void conv_kernel(const float* __restrict__ x,
                                                      const float* __restrict__ offsets) {
    extern __shared__ float sm[];
    float* s_in = sm;
    float* s_w  = sm + O_WS;

    int tid = threadIdx.x;
    int bid = blockIdx.x;
    int b = bid / 200;
    int t = bid - b * 200;
    int y0 = (t / 10) * TTY;
    int x0 = (t % 10) * TTX;

    int r   = tid & 3;
    int ocg = tid >> 2;

    float b1v[3];
#pragma unroll
    for (int o = 0; o < 3; o++) b1v[o] = g_b1[ocg * 3 + o];

    /* prologue: slabs 0 and 1 into buffers 0 and 1 */
    {
        const char* src0 = (const char*)(g_w1s);
        const char* src1 = (const char*)(g_w1s + W_CI_FL);
        uint32_t dst0 = smem_u32(s_w);
        uint32_t dst1 = smem_u32(s_w + W_BUF_FL);
        for (int j = tid; j < W_CI_C16; j += 256)
            cp_async16(dst0 + j * 16, src0 + j * 16);
        cp_commit();
        for (int j = tid; j < W_CI_C16; j += 256)
            cp_async16(dst1 + j * 16, src1 + j * 16);
        cp_commit();
    }

    /* input tile [64][6][12] (cols 0..9 valid) */
    const float* xb = x + (size_t)b * CHN * NY * NX;
    for (int i = tid; i < 64 * 60; i += 256) {
        int ci = i / 60;
        int rem = i - ci * 60;
        int rr = rem / 10;
        int c  = rem - rr * 10;
        int gy = y0 + rr - 1;
        int gx = x0 + c - 1;
        float v = 0.f;
        if ((unsigned)gy < NY && (unsigned)gx < NX) v = xb[(ci * NY + gy) * NX + gx];
        s_in[ci * 72 + rr * 12 + c] = v;
    }
    __syncthreads();

    ull acc[3][4];
#pragma unroll
    for (int o = 0; o < 3; o++)
#pragma unroll
        for (int c = 0; c < 4; c++) acc[o][c] = 0ull;

    int rdbuf = 0;
    int wrbuf = 2;
    for (int ci = 0; ci < 64; ci++) {
        cp_wait1();          /* slab ci resident (only ci+1 may still fly) */
        __syncthreads();     /* all warps finished reading slab ci-1       */
        if (ci + 2 < 64) {
            const char* src = (const char*)(g_w1s + (size_t)(ci + 2) * W_CI_FL);
            uint32_t dst = smem_u32(s_w + wrbuf * W_BUF_FL);
            for (int j = tid; j < W_CI_C16; j += 256)
                cp_async16(dst + j * 16, src + j * 16);
        }
        cp_commit();

        /* 28 scalar weights (27 used) via 7 conflict-free LDS.128 */
        const float* wbase = s_w + rdbuf * W_BUF_FL + ocg * W_OCG_STR;
        float wr[28];
#pragma unroll
        for (int j = 0; j < 7; j++)
            *(float4*)(wr + 4 * j) = *(const float4*)(wbase + 4 * j);

        const float* rbase = s_in + ci * 72 + r * 12;
#pragma unroll
        for (int hr = 0; hr < 3; hr++) {
            const float* rowp = rbase + hr * 12;
            float4 q0 = *(const float4*)rowp;
            float4 q1 = *(const float4*)(rowp + 4);
            float2 q2 = *(const float2*)(rowp + 8);
            ull PA[5] = { pack2f(q0.x, q0.y), pack2f(q0.z, q0.w),
                          pack2f(q1.x, q1.y), pack2f(q1.z, q1.w),
                          pack2f(q2.x, q2.y) };
            ull PB[4] = { pack2f(q0.y, q0.z), pack2f(q0.w, q1.x),
                          pack2f(q1.y, q1.z), pack2f(q1.w, q2.x) };
            const float* wh9 = wr + hr * 9;
#pragma unroll
            for (int o = 0; o < 3; o++) {
                ull wk0 = pack2f(wh9[o * 3 + 0], wh9[o * 3 + 0]);
                ull wk1 = pack2f(wh9[o * 3 + 1], wh9[o * 3 + 1]);
                ull wk2 = pack2f(wh9[o * 3 + 2], wh9[o * 3 + 2]);
#pragma unroll
                for (int c = 0; c < 4; c++) {
                    fma2(acc[o][c], PA[c], wk0);
                    fma2(acc[o][c], PB[c], wk1);
                    fma2(acc[o][c], PA[c + 1], wk2);
                }
            }
        }
        rdbuf = (rdbuf == 2) ? 0 : rdbuf + 1;
        wrbuf = (wrbuf == 2) ? 0 : wrbuf + 1;
    }
    __syncthreads();

    /* ---- post-loop: alias smem to {s_u, s_w2, s_b2} ---- */
    float* s_u  = sm;
    float* s_w2 = sm + O_W2;
    float* s_b2 = sm + O_B2;

#pragma unroll
    for (int o = 0; o < 3; o++) {
        int oc = ocg * 3 + o;
#pragma unroll
        for (int c = 0; c < 4; c++) {
            float2 u = unpack2(acc[o][c]);
            int px = r * TTX + 2 * c;
            s_u[px * S_U_STR + oc]       = fmaxf(u.x + b1v[o], 0.f);
            s_u[(px + 1) * S_U_STR + oc] = fmaxf(u.y + b1v[o], 0.f);
        }
    }
    for (int i = tid; i < NU * 64; i += 256) {
        int u = i >> 6, ci = i & 63;
        s_w2[u * S_W2_STR + ci] = g_w2[i];
    }
    for (int i = tid; i < NU; i += 256) s_b2[i] = g_b2[i];
    __syncthreads();

    /* stage 2: 1x1 convs + sigmoid / bbox decode */
    if (tid < 168) {
        int pxq = tid & 7;
        int g   = tid >> 3;
        float acc2[4][4];
#pragma unroll
        for (int s = 0; s < 4; s++)
#pragma unroll
            for (int p = 0; p < 4; p++) acc2[s][p] = 0.f;

        if (g < 20) {
            const float* w0 = s_w2 + (g * 4 + 0) * S_W2_STR;
            const float* w1 = s_w2 + (g * 4 + 1) * S_W2_STR;
            const float* w2 = s_w2 + (g * 4 + 2) * S_W2_STR;
            const float* w3 = s_w2 + (g * 4 + 3) * S_W2_STR;
#pragma unroll 4
            for (int ci = 0; ci < 64; ci++) {
                float v0 = w0[ci], v1 = w1[ci], v2 = w2[ci], v3 = w3[ci];
#pragma unroll
                for (int p = 0; p < 4; p++) {
                    float uv = s_u[(pxq * 4 + p) * S_U_STR + ci];
                    acc2[0][p] += uv * v0;
                    acc2[1][p] += uv * v1;
                    acc2[2][p] += uv * v2;
                    acc2[3][p] += uv * v3;
                }
            }
#pragma unroll
            for (int s = 0; s < 4; s++) {
                int u = g * 4 + s;
                float bia = s_b2[u];
#pragma unroll
                for (int p = 0; p < 4; p++) {
                    float v = acc2[s][p] + bia;
                    float sig = 1.f / (1.f + expf(-v));
                    int px = pxq * 4 + p;
                    int gy = y0 + (px >> 3), gx = x0 + (px & 7);
                    g_hm[b * KTOT + u * (NY * NX) + gy * NX + gx] = sig;
                }
            }
        } else {
            const float* w0 = s_w2 + 80 * S_W2_STR;
            const float* w1 = s_w2 + 81 * S_W2_STR;
            const float* w2 = s_w2 + 82 * S_W2_STR;
            const float* w3 = s_w2 + 83 * S_W2_STR;
#pragma unroll 4
            for (int ci = 0; ci < 64; ci++) {
                float v0 = w0[ci], v1 = w1[ci], v2 = w2[ci], v3 = w3[ci];
#pragma unroll
                for (int p = 0; p < 4; p++) {
                    float uw = s_u[(pxq * 4 + p) * S_U_STR + 64 + ci];
                    float ur = s_u[(pxq * 4 + p) * S_U_STR + 128 + ci];
                    acc2[0][p] += uw * v0;
                    acc2[1][p] += uw * v1;
                    acc2[2][p] += ur * v2;
                    acc2[3][p] += ur * v3;
                }
            }
            float offx = offsets[b * 3 + 1] * 2.f;
            float offy = offsets[b * 3 + 2] * 2.f;
#pragma unroll
            for (int p = 0; p < 4; p++) {
                int px = pxq * 4 + p;
                int gy = y0 + (px >> 3), gx = x0 + (px & 7);
                float whx = fmaxf(acc2[0][p] + s_b2[80], 0.f);
                float why = fmaxf(acc2[1][p] + s_b2[81], 0.f);
                float rgx = fmaxf(acc2[2][p] + s_b2[82], 0.f);
                float rgy = fmaxf(acc2[3][p] + s_b2[83], 0.f);
                float cx = ((float)gx + offx + rgx) * 4.f;
                float cy = ((float)gy + offy + rgy) * 4.f;
                float* q = g_xywh + ((size_t)b * (NY * NX) + gy * NX + gx) * 4;
                q[0] = cx; q[1] = cy; q[2] = whx * 4.f; q[3] = why * 4.f;
            }
        }
    }
}

/* ---------------- maxima mask: ballots + per-block counts ---------------- */
__global__ void mask_kernel() {
    int bid = blockIdx.x;
    int b = bid / 500;
    int i = (bid - b * 500) * 1024 + threadIdx.x;
    const float* hmp = g_hm + (size_t)b * KTOT;
    float c = hmp[i];
    int ch = i / (NY * NX);
    int rem = i - ch * (NY * NX);
    int y = rem / NX;
    int x = rem - y * NX;
    bool f = true;
#pragma unroll
    for (int dy = -1; dy <= 1; dy++)
#pragma unroll
        for (int dx = -1; dx <= 1; dx++) {
            if (dy == 0 && dx == 0) continue;
            int yy = y + dy, xx = x + dx;
            if ((unsigned)yy < NY && (unsigned)xx < NX)
                f = f && (c >= hmp[ch * (NY * NX) + yy * NX + xx]);
        }
    unsigned bal = __ballot_sync(0xffffffffu, f);
    __shared__ int wc[32];
    int lane = threadIdx.x & 31, w = threadIdx.x >> 5;
    if (lane == 0) {
        g_ballot[bid * 32 + w] = bal;
        wc[w] = __popc(bal);
    }
    __syncthreads();
    if (threadIdx.x == 0) {
        int s = 0;
        for (int k = 0; k < 32; k++) s += wc[k];
        g_bcount[bid] = s;
    }
}

/* ---------------- scan ---------------- */
__global__ void scan_kernel() {
    __shared__ int s[512];
    int tid = threadIdx.x;
    for (int seg = 0; seg < 2; seg++) {
        int v = (tid < 500) ? g_bcount[seg * 500 + tid] : 0;
        s[tid] = v;
        __syncthreads();
        for (int off = 1; off < 512; off <<= 1) {
            int t = (tid >= off) ? s[tid - off] : 0;
            __syncthreads();
            s[tid] += t;
            __syncthreads();
        }
        if (tid < 500) g_boff[seg * 500 + tid] = s[tid] - v;
        if (tid == 499) g_total[seg] = s[499];
        __syncthreads();
    }
}

/* ---------------- fill: resolves rank->pixel directly from ballots -------
   No compact stage.  Each CTA covers 4096 floats = <=50 output rows;
   threads 0..49 cooperatively resolve row->pixel via g_boff binary search
   + ballot popcount walk, then all threads materialize from g_xywh/g_hm. */
#define TOTAL4 (NBATCH * EPB4)           /* 21,760,000 float4 */

__device__ __forceinline__ int resolve_px(int b, int r) {
    const int* boff = g_boff + b * 500;
    int lo = 0, hi = 499;
    while (lo < hi) {                     /* largest blk with boff[blk] <= r */
        int mid = (lo + hi + 1) >> 1;
        if (__ldg(boff + mid) <= r) lo = mid; else hi = mid - 1;
    }
    int k = r - __ldg(boff + lo);
    const unsigned* bw = g_ballot + (size_t)(b * 500 + lo) * 32;
    int wi = 0;
    for (;;) {
        int p = __popc(__ldg(bw + wi));
        if (k < p) break;
        k -= p;
        wi++;
    }
    unsigned bal = __ldg(bw + wi);
    int bit = 0;
    for (;; bit++) {
        if ((bal >> bit) & 1u) {
            if (k == 0) break;
            k--;
        }
    }
    return lo * 1024 + wi * 32 + bit;
}

__global__ __launch_bounds__(256) void fill_kernel(float4* __restrict__ out4) {
    __shared__ int s_px[50];
    int bid = blockIdx.x;
    int b = (bid >= CTAS_PER_BATCH) ? 1 : 0;
    int base4 = bid * 1024;               /* first global float4 of this CTA */
    int e4first = base4 - b * EPB4;
    int cnt = g_total[b];
    int rfirst = (e4first * 4) / NO;
    int tid = threadIdx.x;
    if (tid < 50) {
        int r = rfirst + tid;
        s_px[tid] = (r < cnt) ? resolve_px(b, r) : -1;
    }
    __syncthreads();

#pragma unroll
    for (int k = 0; k < 4; k++) {
        int q = base4 + tid + k * 256;
        if (q >= TOTAL4) continue;
        int e4 = q - b * EPB4;
        int f0 = e4 * 4;
        int r0 = f0 / NO;
        int c0 = f0 - r0 * NO;
        if (r0 >= cnt) {
            out4[q] = make_float4(0.f, 0.f, 0.f, 0.f);
        } else {
            float v[4];
#pragma unroll
            for (int j = 0; j < 4; j++) {
                int c = c0 + j;
                int r = r0;
                if (c >= NO) { c -= NO; r++; }
                float val = 0.f;
                if (r < cnt) {
                    int px = s_px[r - rfirst];
                    int ch = px / (NY * NX);
                    int rem = px - ch * (NY * NX);
                    if (c < 4) {
                        val = __ldg(g_xywh + ((size_t)b * (NY * NX) + rem) * 4 + c);
                    } else if (c == 4) {
                        val = __ldg(g_hm + (size_t)b * KTOT + px);
                    } else {
                        val = (c == 5 + ch) ? 1.0f : 0.f;
                    }
                }
                v[j] = val;
            }
            out4[q] = make_float4(v[0], v[1], v[2], v[3]);
        }
    }
}

/* ---------------- launcher (single stream) ---------------- */
extern "C" void kernel_launch(void* const* d_in, const int* in_sizes, int n_in,
                              void* d_out, int out_size) {
    const float* x       = (const float*)d_in[0];
    const float* offsets = (const float*)d_in[1];
    const float* hm_w1   = (const float*)d_in[2];
    const float* hm_b1   = (const float*)d_in[3];
    const float* hm_w2   = (const float*)d_in[4];
    const float* hm_b2   = (const float*)d_in[5];
    const float* wh_w1   = (const float*)d_in[6];
    const float* wh_b1   = (const float*)d_in[7];
    const float* wh_w2   = (const float*)d_in[8];
    const float* wh_b2   = (const float*)d_in[9];
    const float* reg_w1  = (const float*)d_in[10];
    const float* reg_b1  = (const float*)d_in[11];
    const float* reg_w2  = (const float*)d_in[12];
    const float* reg_b2  = (const float*)d_in[13];

    prep_w1<<<(64 * W_CI_FL + 255) / 256, 256>>>(hm_w1, wh_w1, reg_w1);
    prep_rest<<<(NU * 64 + 255) / 256, 256>>>(hm_b1, wh_b1, reg_b1,
                                              hm_w2, wh_w2, reg_w2,
                                              hm_b2, wh_b2, reg_b2);
    dummy_kernel<<<1, 32>>>();   /* keeps conv at launch index 3 for ncu capture */

    cudaFuncSetAttribute(conv_kernel, cudaFuncAttributeMaxDynamicSharedMemorySize, SMEM_BYTES);
    conv_kernel<<<400, 256, SMEM_BYTES>>>(x, offsets);

    mask_kernel<<<1000, 1024>>>();
    scan_kernel<<<1, 512>>>();

    fill_kernel<<<NBATCH * CTAS_PER_BATCH, 256>>>((float4*)d_out);
}

// round 17
// speedup vs baseline: 1.0671x; 1.0671x over previous
#include <cuda_runtime.h>
#include <math.h>
#include <stdint.h>

#define NBATCH 2
#define CHN 64
#define NY 80
#define NX 80
#define NCLS 80
#define KTOT (NCLS*NY*NX)   /* 512000 */
#define NO 85
#define OC3 192
#define NU 84
#define ELEMS_PER_BATCH (KTOT * NO)      /* 43,520,000 */

typedef unsigned long long ull;

/* ---------------- device scratch ---------------- */
/* conv weights, scalar f32: [ci][ocg(64)][36] (27 used; 144B stride is
   conflict-free across the 8 ocg of a warp)                              */
#define W_OCG_STR 36
#define W_CI_FL  (64 * W_OCG_STR)         /* 2304 floats per ci slab */
#define W_CI_C16 (W_CI_FL / 4)            /* 576 16B chunks per slab */
__device__ float g_w1s[64 * W_CI_FL];
__device__ float g_w2[NU * 64];
__device__ float g_b1[OC3];
__device__ float g_b2[NU];
__device__ float g_hm[NBATCH * KTOT];
__device__ float g_xywh[NBATCH * NY * NX * 4];
__device__ unsigned int g_ballot[1000 * 32];
__device__ int g_bcount[1000];
__device__ int g_boff[1000];
__device__ int g_total[NBATCH];
__device__ float g_rows[NBATCH * KTOT * 8];

/* ---------------- helpers ---------------- */
__device__ __forceinline__ void fma2(ull& d, ull a, ull b) {
    asm("fma.rn.f32x2 %0, %1, %2, %0;" : "+l"(d) : "l"(a), "l"(b));
}
__device__ __forceinline__ float2 unpack2(ull v) {
    float2 r;
    asm("mov.b64 {%0, %1}, %2;" : "=f"(r.x), "=f"(r.y) : "l"(v));
    return r;
}
__device__ __forceinline__ ull pack2f(float lo, float hi) {
    ull r;
    asm("mov.b64 %0, {%1, %2};" : "=l"(r) : "f"(lo), "f"(hi));
    return r;
}
__device__ __forceinline__ void cp_async16(uint32_t s, const void* g) {
    asm volatile("cp.async.cg.shared.global [%0], [%1], 16;" :: "r"(s), "l"(g));
}
__device__ __forceinline__ void cp_commit() {
    asm volatile("cp.async.commit_group;");
}
__device__ __forceinline__ void cp_wait1() {
    asm volatile("cp.async.wait_group 1;");
}
__device__ __forceinline__ uint32_t smem_u32(const void* p) {
    return (uint32_t)__cvta_generic_to_shared(p);
}

/* ---------------- merged weight prep (single launch) ---------------- */
__global__ void prep_all(const float* __restrict__ hm_w1, const float* __restrict__ wh_w1,
                         const float* __restrict__ reg_w1,
                         const float* __restrict__ hm_b1, const float* __restrict__ wh_b1,
                         const float* __restrict__ reg_b1,
                         const float* __restrict__ hm_w2, const float* __restrict__ wh_w2,
                         const float* __restrict__ reg_w2,
                         const float* __restrict__ hm_b2, const float* __restrict__ wh_b2,
                         const float* __restrict__ reg_b2) {
    int idx = blockIdx.x * 256 + threadIdx.x;
    if (idx < 64 * W_CI_FL) {
        int ci   = idx / W_CI_FL;
        int rem  = idx - ci * W_CI_FL;
        int ocg  = rem / W_OCG_STR;
        int j    = rem - ocg * W_OCG_STR;
        float w = 0.f;
        if (j < 27) {
            int hr = j / 9;
            int k9 = j - hr * 9;
            int o  = k9 / 3;
            int k  = k9 - o * 3;
            int oc = ocg * 3 + o;
            const float* src = (oc < 64) ? hm_w1 : (oc < 128) ? wh_w1 : reg_w1;
            int o64 = oc & 63;
            w = src[o64 * 576 + ci * 9 + hr * 3 + k];
        }
        g_w1s[idx] = w;
    }
    if (idx < OC3) g_b1[idx] = (idx < 64) ? hm_b1[idx]
                             : (idx < 128) ? wh_b1[idx - 64] : reg_b1[idx - 128];
    if (idx < NU)  g_b2[idx] = (idx < 80) ? hm_b2[idx]
                             : (idx < 82) ? wh_b2[idx - 80] : reg_b2[idx - 82];
    if (idx < NU * 64) {
        int u = idx >> 6, ci = idx & 63;
        g_w2[idx] = (u < 80) ? hm_w2[u * 64 + ci]
                  : (u < 82) ? wh_w2[(u - 80) * 64 + ci]
                             : reg_w2[(u - 82) * 64 + ci];
    }
}

/* ---------------- fused conv kernel (R11 best: 104.4us) ----------------
   Tile 8x4 px, 256 threads, occ 3.  Thread = (r=tid&3, ocg=tid>>2): 3 oc,
   4 pixel-pairs.  Single input copy; operand pairs via register packing.
   Scalar-f32 weight slabs, ocg-stride 36 (conflict-free), 3-buffer
   cp.async pipeline, one barrier per ci.                                 */
#define TTX 8
#define TTY 4
#define S_IN_FL   (64 * 6 * 12)      /* 4608 floats */
#define O_WS      S_IN_FL
#define W_BUF_FL  W_CI_FL            /* 2304 floats per buffer */
#define MAIN_FL   (O_WS + 3 * W_BUF_FL)    /* 11520 floats = 46 kB */
#define S_U_STR   193
#define S_U_FL    (32 * S_U_STR)
#define O_W2      S_U_FL
#define S_W2_STR  65
#define S_W2_FL   (NU * S_W2_STR)
#define O_B2      (O_W2 + S_W2_FL)
#define POST_FL   (O_B2 + NU)        /* 11720 */
#define SMEM_FL   (POST_FL > MAIN_FL ? POST_FL : MAIN_FL)
#define SMEM_BYTES (SMEM_FL * 4)

__global__ __launch_bounds__(256, 3) void conv_kernel(const float* __restrict__ x,
                                                      const float* __restrict__ offsets) {
    extern __shared__ float sm[];
    float* s_in = sm;
    float* s_w  = sm + O_WS;

    int tid = threadIdx.x;
    int bid = blockIdx.x;
    int b = bid / 200;
    int t = bid - b * 200;
    int y0 = (t / 10) * TTY;
    int x0 = (t % 10) * TTX;

    int r   = tid & 3;
    int ocg = tid >> 2;

    float b1v[3];
#pragma unroll
    for (int o = 0; o < 3; o++) b1v[o] = g_b1[ocg * 3 + o];

    /* prologue: slabs 0 and 1 into buffers 0 and 1 */
    {
        const char* src0 = (const char*)(g_w1s);
        const char* src1 = (const char*)(g_w1s + W_CI_FL);
        uint32_t dst0 = smem_u32(s_w);
        uint32_t dst1 = smem_u32(s_w + W_BUF_FL);
        for (int j = tid; j < W_CI_C16; j += 256)
            cp_async16(dst0 + j * 16, src0 + j * 16);
        cp_commit();
        for (int j = tid; j < W_CI_C16; j += 256)
            cp_async16(dst1 + j * 16, src1 + j * 16);
        cp_commit();
    }

    /* input tile [64][6][12] (cols 0..9 valid) */
    const float* xb = x + (size_t)b * CHN * NY * NX;
    for (int i = tid; i < 64 * 60; i += 256) {
        int ci = i / 60;
        int rem = i - ci * 60;
        int rr = rem / 10;
        int c  = rem - rr * 10;
        int gy = y0 + rr - 1;
        int gx = x0 + c - 1;
        float v = 0.f;
        if ((unsigned)gy < NY && (unsigned)gx < NX) v = xb[(ci * NY + gy) * NX + gx];
        s_in[ci * 72 + rr * 12 + c] = v;
    }
    __syncthreads();

    ull acc[3][4];
#pragma unroll
    for (int o = 0; o < 3; o++)
#pragma unroll
        for (int c = 0; c < 4; c++) acc[o][c] = 0ull;

    int rdbuf = 0;
    int wrbuf = 2;
    for (int ci = 0; ci < 64; ci++) {
        cp_wait1();          /* slab ci resident (only ci+1 may still fly) */
        __syncthreads();     /* all warps finished reading slab ci-1       */
        if (ci + 2 < 64) {
            const char* src = (const char*)(g_w1s + (size_t)(ci + 2) * W_CI_FL);
            uint32_t dst = smem_u32(s_w + wrbuf * W_BUF_FL);
            for (int j = tid; j < W_CI_C16; j += 256)
                cp_async16(dst + j * 16, src + j * 16);
        }
        cp_commit();

        /* 28 scalar weights (27 used) via 7 conflict-free LDS.128 */
        const float* wbase = s_w + rdbuf * W_BUF_FL + ocg * W_OCG_STR;
        float wr[28];
#pragma unroll
        for (int j = 0; j < 7; j++)
            *(float4*)(wr + 4 * j) = *(const float4*)(wbase + 4 * j);

        const float* rbase = s_in + ci * 72 + r * 12;
#pragma unroll
        for (int hr = 0; hr < 3; hr++) {
            const float* rowp = rbase + hr * 12;
            float4 q0 = *(const float4*)rowp;
            float4 q1 = *(const float4*)(rowp + 4);
            float2 q2 = *(const float2*)(rowp + 8);
            ull PA[5] = { pack2f(q0.x, q0.y), pack2f(q0.z, q0.w),
                          pack2f(q1.x, q1.y), pack2f(q1.z, q1.w),
                          pack2f(q2.x, q2.y) };
            ull PB[4] = { pack2f(q0.y, q0.z), pack2f(q0.w, q1.x),
                          pack2f(q1.y, q1.z), pack2f(q1.w, q2.x) };
            const float* wh9 = wr + hr * 9;
#pragma unroll
            for (int o = 0; o < 3; o++) {
                ull wk0 = pack2f(wh9[o * 3 + 0], wh9[o * 3 + 0]);
                ull wk1 = pack2f(wh9[o * 3 + 1], wh9[o * 3 + 1]);
                ull wk2 = pack2f(wh9[o * 3 + 2], wh9[o * 3 + 2]);
#pragma unroll
                for (int c = 0; c < 4; c++) {
                    fma2(acc[o][c], PA[c], wk0);
                    fma2(acc[o][c], PB[c], wk1);
                    fma2(acc[o][c], PA[c + 1], wk2);
                }
            }
        }
        rdbuf = (rdbuf == 2) ? 0 : rdbuf + 1;
        wrbuf = (wrbuf == 2) ? 0 : wrbuf + 1;
    }
    __syncthreads();

    /* ---- post-loop: alias smem to {s_u, s_w2, s_b2} ---- */
    float* s_u  = sm;
    float* s_w2 = sm + O_W2;
    float* s_b2 = sm + O_B2;

#pragma unroll
    for (int o = 0; o < 3; o++) {
        int oc = ocg * 3 + o;
#pragma unroll
        for (int c = 0; c < 4; c++) {
            float2 u = unpack2(acc[o][c]);
            int px = r * TTX + 2 * c;
            s_u[px * S_U_STR + oc]       = fmaxf(u.x + b1v[o], 0.f);
            s_u[(px + 1) * S_U_STR + oc] = fmaxf(u.y + b1v[o], 0.f);
        }
    }
    for (int i = tid; i < NU * 64; i += 256) {
        int u = i >> 6, ci = i & 63;
        s_w2[u * S_W2_STR + ci] = g_w2[i];
    }
    for (int i = tid; i < NU; i += 256) s_b2[i] = g_b2[i];
    __syncthreads();

    /* stage 2: 1x1 convs + sigmoid / bbox decode */
    if (tid < 168) {
        int pxq = tid & 7;
        int g   = tid >> 3;
        float acc2[4][4];
#pragma unroll
        for (int s = 0; s < 4; s++)
#pragma unroll
            for (int p = 0; p < 4; p++) acc2[s][p] = 0.f;

        if (g < 20) {
            const float* w0 = s_w2 + (g * 4 + 0) * S_W2_STR;
            const float* w1 = s_w2 + (g * 4 + 1) * S_W2_STR;
            const float* w2 = s_w2 + (g * 4 + 2) * S_W2_STR;
            const float* w3 = s_w2 + (g * 4 + 3) * S_W2_STR;
#pragma unroll 4
            for (int ci = 0; ci < 64; ci++) {
                float v0 = w0[ci], v1 = w1[ci], v2 = w2[ci], v3 = w3[ci];
#pragma unroll
                for (int p = 0; p < 4; p++) {
                    float uv = s_u[(pxq * 4 + p) * S_U_STR + ci];
                    acc2[0][p] += uv * v0;
                    acc2[1][p] += uv * v1;
                    acc2[2][p] += uv * v2;
                    acc2[3][p] += uv * v3;
                }
            }
#pragma unroll
            for (int s = 0; s < 4; s++) {
                int u = g * 4 + s;
                float bia = s_b2[u];
#pragma unroll
                for (int p = 0; p < 4; p++) {
                    float v = acc2[s][p] + bia;
                    float sig = 1.f / (1.f + expf(-v));
                    int px = pxq * 4 + p;
                    int gy = y0 + (px >> 3), gx = x0 + (px & 7);
                    g_hm[b * KTOT + u * (NY * NX) + gy * NX + gx] = sig;
                }
            }
        } else {
            const float* w0 = s_w2 + 80 * S_W2_STR;
            const float* w1 = s_w2 + 81 * S_W2_STR;
            const float* w2 = s_w2 + 82 * S_W2_STR;
            const float* w3 = s_w2 + 83 * S_W2_STR;
#pragma unroll 4
            for (int ci = 0; ci < 64; ci++) {
                float v0 = w0[ci], v1 = w1[ci], v2 = w2[ci], v3 = w3[ci];
#pragma unroll
                for (int p = 0; p < 4; p++) {
                    float uw = s_u[(pxq * 4 + p) * S_U_STR + 64 + ci];
                    float ur = s_u[(pxq * 4 + p) * S_U_STR + 128 + ci];
                    acc2[0][p] += uw * v0;
                    acc2[1][p] += uw * v1;
                    acc2[2][p] += ur * v2;
                    acc2[3][p] += ur * v3;
                }
            }
            float offx = offsets[b * 3 + 1] * 2.f;
            float offy = offsets[b * 3 + 2] * 2.f;
#pragma unroll
            for (int p = 0; p < 4; p++) {
                int px = pxq * 4 + p;
                int gy = y0 + (px >> 3), gx = x0 + (px & 7);
                float whx = fmaxf(acc2[0][p] + s_b2[80], 0.f);
                float why = fmaxf(acc2[1][p] + s_b2[81], 0.f);
                float rgx = fmaxf(acc2[2][p] + s_b2[82], 0.f);
                float rgy = fmaxf(acc2[3][p] + s_b2[83], 0.f);
                float cx = ((float)gx + offx + rgx) * 4.f;
                float cy = ((float)gy + offy + rgy) * 4.f;
                float* q = g_xywh + ((size_t)b * (NY * NX) + gy * NX + gx) * 4;
                q[0] = cx; q[1] = cy; q[2] = whx * 4.f; q[3] = why * 4.f;
            }
        }
    }
}

/* ---------------- maxima mask: ballots + per-block counts ---------------- */
__global__ void mask_kernel() {
    int bid = blockIdx.x;
    int b = bid / 500;
    int i = (bid - b * 500) * 1024 + threadIdx.x;
    const float* hmp = g_hm + (size_t)b * KTOT;
    float c = hmp[i];
    int ch = i / (NY * NX);
    int rem = i - ch * (NY * NX);
    int y = rem / NX;
    int x = rem - y * NX;
    bool f = true;
#pragma unroll
    for (int dy = -1; dy <= 1; dy++)
#pragma unroll
        for (int dx = -1; dx <= 1; dx++) {
            if (dy == 0 && dx == 0) continue;
            int yy = y + dy, xx = x + dx;
            if ((unsigned)yy < NY && (unsigned)xx < NX)
                f = f && (c >= hmp[ch * (NY * NX) + yy * NX + xx]);
        }
    unsigned bal = __ballot_sync(0xffffffffu, f);
    __shared__ int wc[32];
    int lane = threadIdx.x & 31, w = threadIdx.x >> 5;
    if (lane == 0) {
        g_ballot[bid * 32 + w] = bal;
        wc[w] = __popc(bal);
    }
    __syncthreads();
    if (threadIdx.x == 0) {
        int s = 0;
        for (int k = 0; k < 32; k++) s += wc[k];
        g_bcount[bid] = s;
    }
}

/* ---------------- scan ---------------- */
__global__ void scan_kernel() {
    __shared__ int s[512];
    int tid = threadIdx.x;
    for (int seg = 0; seg < 2; seg++) {
        int v = (tid < 500) ? g_bcount[seg * 500 + tid] : 0;
        s[tid] = v;
        __syncthreads();
        for (int off = 1; off < 512; off <<= 1) {
            int t = (tid >= off) ? s[tid - off] : 0;
            __syncthreads();
            s[tid] += t;
            __syncthreads();
        }
        if (tid < 500) g_boff[seg * 500 + tid] = s[tid] - v;
        if (tid == 499) g_total[seg] = s[499];
        __syncthreads();
    }
}

/* ---------------- compact ---------------- */
__global__ void compact_kernel() {
    int bid = blockIdx.x;
    int b = bid / 500;
    int lane = threadIdx.x & 31, w = threadIdx.x >> 5;
    unsigned bal = g_ballot[bid * 32 + w];
    int f = (bal >> lane) & 1;
    __shared__ int wc[32], we[32];
    if (lane == 0) wc[w] = __popc(bal);
    __syncthreads();
    if (w == 0) {
        int v = wc[lane];
        int inc = v;
#pragma unroll
        for (int off = 1; off < 32; off <<= 1) {
            int t = __shfl_up_sync(0xffffffffu, inc, off);
            if (lane >= off) inc += t;
        }
        we[lane] = inc - v;
    }
    __syncthreads();
    if (f) {
        int i = (bid - b * 500) * 1024 + threadIdx.x;
        int rank = g_boff[bid] + we[w] + __popc(bal & ((1u << lane) - 1u));
        int ch = i / (NY * NX);
        int rem = i - ch * (NY * NX);
        int y = rem / NX;
        int x = rem - y * NX;
        const float* q = g_xywh + ((size_t)b * (NY * NX) + y * NX + x) * 4;
        float* rd = g_rows + ((size_t)b * KTOT + rank) * 8;
        float4 lo = make_float4(q[0], q[1], q[2], q[3]);
        float4 hi = make_float4(g_hm[(size_t)b * KTOT + i], (float)ch, 0.f, 0.f);
        *(float4*)(rd)     = lo;
        *(float4*)(rd + 4) = hi;
    }
}

/* ---------------- fill: write entire output exactly once ---------------- */
#define TOTAL4 (NBATCH * ELEMS_PER_BATCH / 4)   /* 21,760,000 */

__global__ __launch_bounds__(256) void fill_kernel(float4* __restrict__ out4) {
    int base = blockIdx.x * 1024 + threadIdx.x;
#pragma unroll
    for (int k = 0; k < 4; k++) {
        int q = base + k * 256;
        if (q >= TOTAL4) continue;
        int f0 = q * 4;
        int b = (f0 >= ELEMS_PER_BATCH) ? 1 : 0;
        int e = f0 - b * ELEMS_PER_BATCH;
        int r0 = e / NO;
        int c0 = e - r0 * NO;
        int cnt = g_total[b];
        if (r0 >= cnt) {
            out4[q] = make_float4(0.f, 0.f, 0.f, 0.f);
        } else {
            float v[4];
#pragma unroll
            for (int j = 0; j < 4; j++) {
                int c = c0 + j;
                int r = r0;
                if (c >= NO) { c -= NO; r++; }
                float val = 0.f;
                if (r < cnt) {
                    const float* rd = g_rows + ((size_t)b * KTOT + r) * 8;
                    if (c < 5) val = __ldg(rd + c);
                    else {
                        int ch = (int)__ldg(rd + 5);
                        val = (c == 5 + ch) ? 1.0f : 0.f;
                    }
                }
                v[j] = val;
            }
            out4[q] = make_float4(v[0], v[1], v[2], v[3]);
        }
    }
}

/* ---------------- launcher (single stream, 5 launches) ---------------- */
extern "C" void kernel_launch(void* const* d_in, const int* in_sizes, int n_in,
                              void* d_out, int out_size) {
    const float* x       = (const float*)d_in[0];
    const float* offsets = (const float*)d_in[1];
    const float* hm_w1   = (const float*)d_in[2];
    const float* hm_b1   = (const float*)d_in[3];
    const float* hm_w2   = (const float*)d_in[4];
    const float* hm_b2   = (const float*)d_in[5];
    const float* wh_w1   = (const float*)d_in[6];
    const float* wh_b1   = (const float*)d_in[7];
    const float* wh_w2   = (const float*)d_in[8];
    const float* wh_b2   = (const float*)d_in[9];
    const float* reg_w1  = (const float*)d_in[10];
    const float* reg_b1  = (const float*)d_in[11];
    const float* reg_w2  = (const float*)d_in[12];
    const float* reg_b2  = (const float*)d_in[13];

    prep_all<<<(64 * W_CI_FL + 255) / 256, 256>>>(hm_w1, wh_w1, reg_w1,
                                                  hm_b1, wh_b1, reg_b1,
                                                  hm_w2, wh_w2, reg_w2,
                                                  hm_b2, wh_b2, reg_b2);

    cudaFuncSetAttribute(conv_kernel, cudaFuncAttributeMaxDynamicSharedMemorySize, SMEM_BYTES);
    conv_kernel<<<400, 256, SMEM_BYTES>>>(x, offsets);

    mask_kernel<<<1000, 1024>>>();
    scan_kernel<<<1, 512>>>();
    compact_kernel<<<1000, 1024>>>();

    fill_kernel<<<(TOTAL4 + 1023) / 1024, 256>>>((float4*)d_out);
}